// round 4
// baseline (speedup 1.0000x reference)
#include <cuda_runtime.h>
#include <cstdint>
#include <cstddef>

// Problem constants
#define Tn   256
#define Bn   64
#define Dn   1024
#define Hn   512
#define Gn   2048   // 4H
#define PBn  128    // P*B party streams
#define SRn  192    // stream rows per timestep: 64 (rnn) + 128 (rnnp)
#define LANES 384   // SRn * 2 directions

// ---------------- scratch (static device globals; no allocations) -------------
__device__ float g_Up [Tn * PBn * Dn];            // party-gathered inputs
__device__ float g_xg [(size_t)Tn * SRn * 2 * Gn];// input projections (per layer)
__device__ float g_h0 [(size_t)Tn * SRn * 2 * Hn];// layer0 h outputs (fwd|bwd)
__device__ float g_h1 [(size_t)Tn * SRn * 2 * Hn];// layer1 h outputs
__device__ float g_hA [LANES * Hn];               // h double buffer A
__device__ float g_hB [LANES * Hn];               // h double buffer B
__device__ float g_cc [LANES * Hn];               // cell state
__device__ int   g_spk[Bn * Tn];
__device__ int   g_pos[Bn * Tn];

// ---------------- helpers ------------------------------------------------------
__device__ __forceinline__ void ffma2(unsigned long long &d,
                                      unsigned long long a,
                                      unsigned long long b) {
    asm("fma.rn.f32x2 %0, %1, %2, %0;" : "+l"(d) : "l"(a), "l"(b));
}
__device__ __forceinline__ unsigned long long dup2(float x) {
    unsigned int u = __float_as_uint(x);
    return ((unsigned long long)u << 32) | (unsigned long long)u;
}
__device__ __forceinline__ float f2lo(unsigned long long v) {
    return __uint_as_float((unsigned int)(v & 0xffffffffULL));
}
__device__ __forceinline__ float f2hi(unsigned long long v) {
    return __uint_as_float((unsigned int)(v >> 32));
}
__device__ __forceinline__ float sigm(float x) {
    return __fdividef(1.f, 1.f + __expf(-x));
}

// ---------------- zero the party buffer ----------------------------------------
__global__ void k_zero_up() {
    size_t n4 = (size_t)Tn * PBn * Dn / 4;
    float4 z = make_float4(0.f, 0.f, 0.f, 0.f);
    float4* p = (float4*)g_Up;
    for (size_t i = (size_t)blockIdx.x * blockDim.x + threadIdx.x; i < n4;
         i += (size_t)gridDim.x * blockDim.x)
        p[i] = z;
}

// ---------------- speaker rank precompute --------------------------------------
__global__ void k_prep(const float* __restrict__ qmask) {
    int b = threadIdx.x;
    if (b >= Bn) return;
    int c0 = 0, c1 = 0;
    for (int t = 0; t < Tn; t++) {
        float q1 = qmask[(b * Tn + t) * 2 + 1];
        int p = (q1 > 0.5f) ? 1 : 0;
        g_spk[b * Tn + t] = p;
        g_pos[b * Tn + t] = p ? (c1++) : (c0++);
    }
}

// ---------------- party gather (scatter U rows into party streams) -------------
__global__ void k_scatter(const float* __restrict__ U) {
    int tb = blockIdx.x;
    int t = tb >> 6, b = tb & 63;
    int p = g_spk[b * Tn + t];
    int r = g_pos[b * Tn + t];
    int s = p * Bn + b;
    const float4* src = (const float4*)(U + (size_t)(t * Bn + b) * Dn);
    float4*       dst = (float4*)(g_Up + (size_t)(r * PBn + s) * Dn);
    dst[threadIdx.x] = src[threadIdx.x];   // 256 threads * float4 = 1024 floats
}

// ---------------- input-projection GEMM ----------------------------------------
// g_xg[((t*192+s)*2+dir)*2048 + n] = x[t,s,:] . W[dir][n,:] + bias[dir][n]
// Tile: 64 rows x 256 cols, K=1024 in chunks of 16, 256 threads, f32x2 packed.
__global__ __launch_bounds__(256) void k_xg(
    int layer, const float* __restrict__ U,
    const float* __restrict__ WihR, const float* __restrict__ bR,
    const float* __restrict__ WihP, const float* __restrict__ bP)
{
    __shared__ __align__(16) unsigned long long a2s[16][66]; // duplicated x vals
    __shared__ __align__(16) float              bs [16][260]; // weights [k][n]

    int m0  = blockIdx.y * 64;
    int n0g = blockIdx.x * 256;
    int dir = n0g >> 11;
    int n0  = n0g & 2047;
    int t   = m0 / SRn;
    int s0  = m0 - t * SRn;          // 0, 64 or 128
    bool isR = (s0 == 0);

    const float* W    = (isR ? WihR : WihP) + ((size_t)dir * Gn + n0) * 1024;
    const float* bias = (isR ? bR : bP) + dir * Gn + n0;

    int tid = threadIdx.x;
    int tx = tid & 31, ty = tid >> 5;

    int arow = tid >> 2;      // 0..63
    int akv  = tid & 3;       // 0..3
    const float* xrow;
    {
        int s = s0 + arow;
        if (layer == 0) {
            if (isR) xrow = U    + (size_t)(t * Bn  + s) * 1024;
            else     xrow = g_Up + (size_t)(t * PBn + (s - 64)) * 1024;
        } else {
            xrow = g_h0 + (size_t)(t * SRn + s) * 1024;
        }
    }

    unsigned long long acc[8][4];
#pragma unroll
    for (int i = 0; i < 8; i++)
#pragma unroll
        for (int j = 0; j < 4; j++) acc[i][j] = 0ULL;

    for (int k0 = 0; k0 < 1024; k0 += 16) {
        // stage A (duplicated for f32x2 broadcast)
        float4 av = *(const float4*)(xrow + k0 + akv * 4);
        a2s[akv * 4 + 0][arow] = dup2(av.x);
        a2s[akv * 4 + 1][arow] = dup2(av.y);
        a2s[akv * 4 + 2][arow] = dup2(av.z);
        a2s[akv * 4 + 3][arow] = dup2(av.w);
        // stage B: 256 cols x 16 k, transpose k-major -> [k][n]
#pragma unroll
        for (int i = 0; i < 4; i++) {
            int nl = (tid >> 2) + i * 64;
            float4 wv = *(const float4*)(W + (size_t)nl * 1024 + k0 + akv * 4);
            bs[akv * 4 + 0][nl] = wv.x;
            bs[akv * 4 + 1][nl] = wv.y;
            bs[akv * 4 + 2][nl] = wv.z;
            bs[akv * 4 + 3][nl] = wv.w;
        }
        __syncthreads();
#pragma unroll
        for (int kk = 0; kk < 16; kk++) {
            ulonglong2 A0 = *(const ulonglong2*)&a2s[kk][ty * 4];
            ulonglong2 A1 = *(const ulonglong2*)&a2s[kk][ty * 4 + 2];
            ulonglong2 A2 = *(const ulonglong2*)&a2s[kk][32 + ty * 4];
            ulonglong2 A3 = *(const ulonglong2*)&a2s[kk][32 + ty * 4 + 2];
            ulonglong2 B0 = *(const ulonglong2*)&bs[kk][tx * 4];
            ulonglong2 B1 = *(const ulonglong2*)&bs[kk][128 + tx * 4];
            unsigned long long ar[8] = {A0.x, A0.y, A1.x, A1.y, A2.x, A2.y, A3.x, A3.y};
            unsigned long long bp[4] = {B0.x, B0.y, B1.x, B1.y};
#pragma unroll
            for (int r = 0; r < 8; r++)
#pragma unroll
                for (int c = 0; c < 4; c++) ffma2(acc[r][c], ar[r], bp[c]);
        }
        __syncthreads();
    }

    // epilogue: add bias, store
#pragma unroll
    for (int rh = 0; rh < 2; rh++) {
#pragma unroll
        for (int rq = 0; rq < 4; rq++) {
            int r = (rh ? 32 : 0) + ty * 4 + rq;
            int s = s0 + r;
            float* orow = g_xg + ((size_t)((t * SRn + s) * 2 + dir)) * Gn + n0;
            int ai = rh * 4 + rq;
#pragma unroll
            for (int ch = 0; ch < 2; ch++) {
                int c = (ch ? 128 : 0) + tx * 4;
                unsigned long long p0 = acc[ai][ch * 2 + 0];
                unsigned long long p1 = acc[ai][ch * 2 + 1];
                float4 ov;
                ov.x = f2lo(p0) + bias[c + 0];
                ov.y = f2hi(p0) + bias[c + 1];
                ov.z = f2lo(p1) + bias[c + 2];
                ov.w = f2hi(p1) + bias[c + 3];
                *(float4*)(orow + c) = ov;
            }
        }
    }
}

// ---------------- fused recurrent step (GEMM + LSTM cell) ----------------------
// One launch per timestep index k. Grid (12, 8): 32 lanes x 64 h-indices (x 4 gates).
__global__ __launch_bounds__(256) void k_step(
    int k, int layer,
    const float* __restrict__ WhhR, const float* __restrict__ WhhP)
{
    __shared__ __align__(16) unsigned long long a2s[16][34]; // h_prev duplicated
    __shared__ __align__(16) float              ws [16][258]; // weight tile [k][col]

    int rg = blockIdx.x;           // 0..11 : lane group of 32
    int jg = blockIdx.y;           // 0..7  : h-index group of 64
    int l0 = rg * 32;
    int j0 = jg * 64;

    bool isR = (l0 < 128);
    int  dir = isR ? (l0 >= 64 ? 1 : 0) : (l0 >= 256 ? 1 : 0);
    int  L0seg = isR ? (dir ? 64 : 0) : (dir ? 256 : 128);
    int  s_base = (isR ? 0 : 64) + (l0 - L0seg);
    int  time = dir ? (Tn - 1 - k) : k;

    const float* W = (isR ? WhhR : WhhP) + (size_t)dir * Gn * Hn;

    int parity = k & 1;
    const float* hprev = parity ? g_hB : g_hA;
    float*       hnext = parity ? g_hA : g_hB;
    float*       hbuf  = layer ? g_h1 : g_h0;

    int tid = threadIdx.x;
    int tx = tid & 31, ty = tid >> 5;

    unsigned long long acc[4][4];   // [row r][gate g], pair over j = j0+2tx, +1
#pragma unroll
    for (int i = 0; i < 4; i++)
#pragma unroll
        for (int j = 0; j < 4; j++) acc[i][j] = 0ULL;

    if (k > 0) {
        for (int k0 = 0; k0 < Hn; k0 += 16) {
            // stage h_prev: 32 rows x 16 k, duplicated
#pragma unroll
            for (int e = 0; e < 2; e++) {
                int idx = tid + e * 256;
                int row = idx >> 4, kv = idx & 15;
                a2s[kv][row] = dup2(hprev[(size_t)(l0 + row) * Hn + k0 + kv]);
            }
            // stage weights: 256 gate-cols (4 gates x 64 j) x 16 k
#pragma unroll
            for (int i = 0; i < 4; i++) {
                int jj = tid >> 2;              // 0..63
                int nl = jj + i * 64;           // gate = i
                int kvq = tid & 3;
                const float4 wv = *(const float4*)(
                    W + (size_t)(i * Hn + j0 + jj) * Hn + k0 + kvq * 4);
                ws[kvq * 4 + 0][nl] = wv.x;
                ws[kvq * 4 + 1][nl] = wv.y;
                ws[kvq * 4 + 2][nl] = wv.z;
                ws[kvq * 4 + 3][nl] = wv.w;
            }
            __syncthreads();
#pragma unroll
            for (int kk = 0; kk < 16; kk++) {
                unsigned long long ar[4];
#pragma unroll
                for (int r = 0; r < 4; r++) ar[r] = a2s[kk][ty * 4 + r];
                unsigned long long bg[4];
#pragma unroll
                for (int g = 0; g < 4; g++)
                    bg[g] = *(const unsigned long long*)&ws[kk][g * 64 + 2 * tx];
#pragma unroll
                for (int r = 0; r < 4; r++)
#pragma unroll
                    for (int g = 0; g < 4; g++) ffma2(acc[r][g], ar[r], bg[g]);
            }
            __syncthreads();
        }
    }

    // epilogue: add xg, LSTM cell update, store c/h
#pragma unroll
    for (int r = 0; r < 4; r++) {
        int row = ty * 4 + r;             // 0..31
        int L = l0 + row;
        int s = s_base + row;
        const float* xgrow = g_xg
            + ((size_t)((time * SRn + s) * 2 + dir)) * Gn + j0 + 2 * tx;
        float2 xi = *(const float2*)(xgrow + 0 * Hn);
        float2 xf = *(const float2*)(xgrow + 1 * Hn);
        float2 xg = *(const float2*)(xgrow + 2 * Hn);
        float2 xo = *(const float2*)(xgrow + 3 * Hn);

        float pi0 = f2lo(acc[r][0]) + xi.x, pi1 = f2hi(acc[r][0]) + xi.y;
        float pf0 = f2lo(acc[r][1]) + xf.x, pf1 = f2hi(acc[r][1]) + xf.y;
        float pg0 = f2lo(acc[r][2]) + xg.x, pg1 = f2hi(acc[r][2]) + xg.y;
        float po0 = f2lo(acc[r][3]) + xo.x, po1 = f2hi(acc[r][3]) + xo.y;

        float i0 = sigm(pi0), i1 = sigm(pi1);
        float f0 = sigm(pf0), f1 = sigm(pf1);
        float gg0 = tanhf(pg0), gg1 = tanhf(pg1);
        float o0 = sigm(po0), o1 = sigm(po1);

        float c0o = 0.f, c1o = 0.f;
        size_t cidx = (size_t)L * Hn + j0 + 2 * tx;
        if (k > 0) {
            float2 cv = *(const float2*)(g_cc + cidx);
            c0o = cv.x; c1o = cv.y;
        }
        float cn0 = f0 * c0o + i0 * gg0;
        float cn1 = f1 * c1o + i1 * gg1;
        float h0v = o0 * tanhf(cn0);
        float h1v = o1 * tanhf(cn1);

        *(float2*)(g_cc + cidx) = make_float2(cn0, cn1);
        *(float2*)(hnext + cidx) = make_float2(h0v, h1v);
        float* hb = hbuf + (size_t)(time * SRn + s) * (2 * Hn) + dir * Hn + j0 + 2 * tx;
        *(float2*)hb = make_float2(h0v, h1v);
    }
}

// ---------------- output assembly ----------------------------------------------
__global__ void k_out(float* __restrict__ out) {
    int tb = blockIdx.x;
    int t = tb >> 6, b = tb & 63;
    int p = g_spk[b * Tn + t];
    int r = g_pos[b * Tn + t];
    const float4* us = (const float4*)(g_h1 + (size_t)(t * SRn + b) * 1024);
    const float4* up = (const float4*)(g_h1 + (size_t)(r * SRn + 64 + p * 64 + b) * 1024);
    float4* o = (float4*)(out + (size_t)tb * 2048);
    int tid = threadIdx.x;
    o[tid]       = us[tid];   // first 1024 floats: U_s
    o[256 + tid] = up[tid];   // next 1024 floats: U_p
}

// ---------------- launcher ------------------------------------------------------
extern "C" void kernel_launch(void* const* d_in, const int* in_sizes, int n_in,
                              void* d_out, int out_size) {
    const float* U     = (const float*)d_in[0];
    const float* qmask = (const float*)d_in[1];
    const float* rW0 = (const float*)d_in[3];
    const float* rU0 = (const float*)d_in[4];
    const float* rb0 = (const float*)d_in[5];
    const float* rW1 = (const float*)d_in[6];
    const float* rU1 = (const float*)d_in[7];
    const float* rb1 = (const float*)d_in[8];
    const float* pW0 = (const float*)d_in[9];
    const float* pU0 = (const float*)d_in[10];
    const float* pb0 = (const float*)d_in[11];
    const float* pW1 = (const float*)d_in[12];
    const float* pU1 = (const float*)d_in[13];
    const float* pb1 = (const float*)d_in[14];
    float* out = (float*)d_out;

    k_zero_up<<<2048, 256>>>();
    k_prep<<<1, 64>>>(qmask);
    k_scatter<<<Tn * Bn, 256>>>(U);

    dim3 gx(16, (Tn * SRn) / 64);   // 16 x 768

    k_xg<<<gx, 256>>>(0, U, rW0, rb0, pW0, pb0);
    for (int k = 0; k < Tn; k++)
        k_step<<<dim3(12, 8), 256>>>(k, 0, rU0, pU0);

    k_xg<<<gx, 256>>>(1, U, rW1, rb1, pW1, pb1);
    for (int k = 0; k < Tn; k++)
        k_step<<<dim3(12, 8), 256>>>(k, 1, rU1, pU1);

    k_out<<<Tn * Bn, 256>>>(out);
}

// round 5
// speedup vs baseline: 1.0619x; 1.0619x over previous
#include <cuda_runtime.h>
#include <cstdint>
#include <cstddef>

// Problem constants
#define Tn   256
#define Bn   64
#define Dn   1024
#define Hn   512
#define Gn   2048   // 4H
#define PBn  128    // P*B party streams
#define SRn  192    // stream rows per timestep: 64 (rnn) + 128 (rnnp)
#define LANES 384   // SRn * 2 directions

// ---------------- scratch (static device globals; no allocations) -------------
__device__ float g_Up [Tn * PBn * Dn];            // party-gathered inputs
__device__ float g_xg [(size_t)Tn * SRn * 2 * Gn];// input projections (per layer)
__device__ float g_h0 [(size_t)Tn * SRn * 2 * Hn];// layer0 h outputs (fwd|bwd)
__device__ float g_h1 [(size_t)Tn * SRn * 2 * Hn];// layer1 h outputs
__device__ float g_hA [LANES * Hn];               // h double buffer A
__device__ float g_hB [LANES * Hn];               // h double buffer B
__device__ float g_cc [LANES * Hn];               // cell state
__device__ int   g_spk[Bn * Tn];
__device__ int   g_pos[Bn * Tn];
__device__ unsigned g_bar[12];                    // per-row-group step barriers

// ---------------- helpers ------------------------------------------------------
__device__ __forceinline__ void ffma2(unsigned long long &d,
                                      unsigned long long a,
                                      unsigned long long b) {
    asm("fma.rn.f32x2 %0, %1, %2, %0;" : "+l"(d) : "l"(a), "l"(b));
}
__device__ __forceinline__ unsigned long long dup2(float x) {
    unsigned int u = __float_as_uint(x);
    return ((unsigned long long)u << 32) | (unsigned long long)u;
}
__device__ __forceinline__ float f2lo(unsigned long long v) {
    return __uint_as_float((unsigned int)(v & 0xffffffffULL));
}
__device__ __forceinline__ float f2hi(unsigned long long v) {
    return __uint_as_float((unsigned int)(v >> 32));
}
__device__ __forceinline__ float sigm(float x) {
    return __fdividef(1.f, 1.f + __expf(-x));
}

// ---------------- zero the party buffer ----------------------------------------
__global__ void k_zero_up() {
    size_t n4 = (size_t)Tn * PBn * Dn / 4;
    float4 z = make_float4(0.f, 0.f, 0.f, 0.f);
    float4* p = (float4*)g_Up;
    for (size_t i = (size_t)blockIdx.x * blockDim.x + threadIdx.x; i < n4;
         i += (size_t)gridDim.x * blockDim.x)
        p[i] = z;
}

// ---------------- barrier counters reset ----------------------------------------
__global__ void k_bzero() {
    if (threadIdx.x < 12) g_bar[threadIdx.x] = 0u;
}

// ---------------- speaker rank precompute --------------------------------------
__global__ void k_prep(const float* __restrict__ qmask) {
    int b = threadIdx.x;
    if (b >= Bn) return;
    int c0 = 0, c1 = 0;
    for (int t = 0; t < Tn; t++) {
        float q1 = qmask[(b * Tn + t) * 2 + 1];
        int p = (q1 > 0.5f) ? 1 : 0;
        g_spk[b * Tn + t] = p;
        g_pos[b * Tn + t] = p ? (c1++) : (c0++);
    }
}

// ---------------- party gather (scatter U rows into party streams) -------------
__global__ void k_scatter(const float* __restrict__ U) {
    int tb = blockIdx.x;
    int t = tb >> 6, b = tb & 63;
    int p = g_spk[b * Tn + t];
    int r = g_pos[b * Tn + t];
    int s = p * Bn + b;
    const float4* src = (const float4*)(U + (size_t)(t * Bn + b) * Dn);
    float4*       dst = (float4*)(g_Up + (size_t)(r * PBn + s) * Dn);
    dst[threadIdx.x] = src[threadIdx.x];   // 256 threads * float4 = 1024 floats
}

// ---------------- input-projection GEMM (software-pipelined) --------------------
// g_xg[((t*192+s)*2+dir)*2048 + n] = x[t,s,:] . W[dir][n,:] + bias[dir][n]
// Tile: 64 rows x 256 cols, K=1024 in chunks of 16, 256 threads, f32x2 packed.
// Next chunk's global loads are issued before the compute phase so their
// latency hides under the 512-FFMA2 compute.
__global__ __launch_bounds__(256, 2) void k_xg(
    int layer, const float* __restrict__ U,
    const float* __restrict__ WihR, const float* __restrict__ bR,
    const float* __restrict__ WihP, const float* __restrict__ bP)
{
    __shared__ __align__(16) unsigned long long a2s[16][66]; // duplicated x vals
    __shared__ __align__(16) float              bs [16][260]; // weights [k][n]

    int m0  = blockIdx.y * 64;
    int n0g = blockIdx.x * 256;
    int dir = n0g >> 11;
    int n0  = n0g & 2047;
    int t   = m0 / SRn;
    int s0  = m0 - t * SRn;          // 0, 64 or 128
    bool isR = (s0 == 0);

    const float* W    = (isR ? WihR : WihP) + ((size_t)dir * Gn + n0) * 1024;
    const float* bias = (isR ? bR : bP) + dir * Gn + n0;

    int tid = threadIdx.x;
    int tx = tid & 31, ty = tid >> 5;

    int arow = tid >> 2;      // 0..63
    int akv  = tid & 3;       // 0..3
    const float* xrow;
    {
        int s = s0 + arow;
        if (layer == 0) {
            if (isR) xrow = U    + (size_t)(t * Bn  + s) * 1024;
            else     xrow = g_Up + (size_t)(t * PBn + (s - 64)) * 1024;
        } else {
            xrow = g_h0 + (size_t)(t * SRn + s) * 1024;
        }
    }
    const float* wrow = W + (size_t)(tid >> 2) * 1024 + akv * 4;

    unsigned long long acc[8][4];
#pragma unroll
    for (int i = 0; i < 8; i++)
#pragma unroll
        for (int j = 0; j < 4; j++) acc[i][j] = 0ULL;

    // prologue: load chunk 0 into registers
    float4 av = *(const float4*)(xrow + akv * 4);
    float4 wv0 = *(const float4*)(wrow);
    float4 wv1 = *(const float4*)(wrow + 64 * 1024);
    float4 wv2 = *(const float4*)(wrow + 128 * 1024);
    float4 wv3 = *(const float4*)(wrow + 192 * 1024);

    for (int k0 = 0; k0 < 1024; k0 += 16) {
        // store staged chunk into shared
        a2s[akv * 4 + 0][arow] = dup2(av.x);
        a2s[akv * 4 + 1][arow] = dup2(av.y);
        a2s[akv * 4 + 2][arow] = dup2(av.z);
        a2s[akv * 4 + 3][arow] = dup2(av.w);
        {
            int nl = tid >> 2;
            bs[akv * 4 + 0][nl      ] = wv0.x;
            bs[akv * 4 + 1][nl      ] = wv0.y;
            bs[akv * 4 + 2][nl      ] = wv0.z;
            bs[akv * 4 + 3][nl      ] = wv0.w;
            bs[akv * 4 + 0][nl +  64] = wv1.x;
            bs[akv * 4 + 1][nl +  64] = wv1.y;
            bs[akv * 4 + 2][nl +  64] = wv1.z;
            bs[akv * 4 + 3][nl +  64] = wv1.w;
            bs[akv * 4 + 0][nl + 128] = wv2.x;
            bs[akv * 4 + 1][nl + 128] = wv2.y;
            bs[akv * 4 + 2][nl + 128] = wv2.z;
            bs[akv * 4 + 3][nl + 128] = wv2.w;
            bs[akv * 4 + 0][nl + 192] = wv3.x;
            bs[akv * 4 + 1][nl + 192] = wv3.y;
            bs[akv * 4 + 2][nl + 192] = wv3.z;
            bs[akv * 4 + 3][nl + 192] = wv3.w;
        }
        __syncthreads();

        // issue next chunk's loads (latency hides under compute below)
        if (k0 + 16 < 1024) {
            int kn = k0 + 16;
            av  = *(const float4*)(xrow + kn + akv * 4);
            wv0 = *(const float4*)(wrow + kn);
            wv1 = *(const float4*)(wrow + 64 * 1024 + kn);
            wv2 = *(const float4*)(wrow + 128 * 1024 + kn);
            wv3 = *(const float4*)(wrow + 192 * 1024 + kn);
        }

#pragma unroll
        for (int kk = 0; kk < 16; kk++) {
            ulonglong2 A0 = *(const ulonglong2*)&a2s[kk][ty * 4];
            ulonglong2 A1 = *(const ulonglong2*)&a2s[kk][ty * 4 + 2];
            ulonglong2 A2 = *(const ulonglong2*)&a2s[kk][32 + ty * 4];
            ulonglong2 A3 = *(const ulonglong2*)&a2s[kk][32 + ty * 4 + 2];
            ulonglong2 B0 = *(const ulonglong2*)&bs[kk][tx * 4];
            ulonglong2 B1 = *(const ulonglong2*)&bs[kk][128 + tx * 4];
            unsigned long long ar[8] = {A0.x, A0.y, A1.x, A1.y, A2.x, A2.y, A3.x, A3.y};
            unsigned long long bp[4] = {B0.x, B0.y, B1.x, B1.y};
#pragma unroll
            for (int r = 0; r < 8; r++)
#pragma unroll
                for (int c = 0; c < 4; c++) ffma2(acc[r][c], ar[r], bp[c]);
        }
        __syncthreads();
    }

    // epilogue: add bias, store
#pragma unroll
    for (int rh = 0; rh < 2; rh++) {
#pragma unroll
        for (int rq = 0; rq < 4; rq++) {
            int r = (rh ? 32 : 0) + ty * 4 + rq;
            int s = s0 + r;
            float* orow = g_xg + ((size_t)((t * SRn + s) * 2 + dir)) * Gn + n0;
            int ai = rh * 4 + rq;
#pragma unroll
            for (int ch = 0; ch < 2; ch++) {
                int c = (ch ? 128 : 0) + tx * 4;
                unsigned long long p0 = acc[ai][ch * 2 + 0];
                unsigned long long p1 = acc[ai][ch * 2 + 1];
                float4 ov;
                ov.x = f2lo(p0) + bias[c + 0];
                ov.y = f2hi(p0) + bias[c + 1];
                ov.z = f2lo(p1) + bias[c + 2];
                ov.w = f2hi(p1) + bias[c + 3];
                *(float4*)(orow + c) = ov;
            }
        }
    }
}

// ---------------- persistent recurrence (all 256 steps in one launch) ----------
// Grid (12, 8): 96 blocks, all resident (<=148 SMs). Block (rg, jg) owns
// lanes [32rg, 32rg+32) x h-indices [64jg, 64jg+64) x all 4 gates.
// Cross-step dependency: block reads h rows of its OWN lane group only, which
// are written by the 8 jg-blocks sharing rg -> per-rg barrier of 8 arrivals.
__global__ __launch_bounds__(256) void k_rec(
    int layer,
    const float* __restrict__ WhhR, const float* __restrict__ WhhP)
{
    __shared__ __align__(16) unsigned long long a2s[16][34]; // h_prev duplicated
    __shared__ __align__(16) float              ws [16][258]; // weight tile [k][col]

    int rg = blockIdx.x;           // 0..11 : lane group of 32
    int jg = blockIdx.y;           // 0..7  : h-index group of 64
    int l0 = rg * 32;
    int j0 = jg * 64;

    bool isR = (l0 < 128);
    int  dir = isR ? (l0 >= 64 ? 1 : 0) : (l0 >= 256 ? 1 : 0);
    int  L0seg = isR ? (dir ? 64 : 0) : (dir ? 256 : 128);
    int  s_base = (isR ? 0 : 64) + (l0 - L0seg);

    const float* W = (isR ? WhhR : WhhP) + (size_t)dir * Gn * Hn;
    float* hbuf = layer ? g_h1 : g_h0;

    int tid = threadIdx.x;
    int tx = tid & 31, ty = tid >> 5;

    for (int k = 0; k < Tn; k++) {
        int time = dir ? (Tn - 1 - k) : k;
        int parity = k & 1;
        const float* hprev = parity ? g_hB : g_hA;
        float*       hnext = parity ? g_hA : g_hB;

        unsigned long long acc[4][4];   // [row r][gate g]; pair j = j0+2tx, +1
#pragma unroll
        for (int i = 0; i < 4; i++)
#pragma unroll
            for (int j = 0; j < 4; j++) acc[i][j] = 0ULL;

        if (k > 0) {
            for (int k0 = 0; k0 < Hn; k0 += 16) {
                // stage h_prev: 32 rows x 16 k, duplicated
#pragma unroll
                for (int e = 0; e < 2; e++) {
                    int idx = tid + e * 256;
                    int row = idx >> 4, kv = idx & 15;
                    a2s[kv][row] = dup2(hprev[(size_t)(l0 + row) * Hn + k0 + kv]);
                }
                // stage weights: 256 gate-cols (4 gates x 64 j) x 16 k
#pragma unroll
                for (int i = 0; i < 4; i++) {
                    int jj = tid >> 2;              // 0..63
                    int nl = jj + i * 64;           // gate = i
                    int kvq = tid & 3;
                    const float4 wv = *(const float4*)(
                        W + (size_t)(i * Hn + j0 + jj) * Hn + k0 + kvq * 4);
                    ws[kvq * 4 + 0][nl] = wv.x;
                    ws[kvq * 4 + 1][nl] = wv.y;
                    ws[kvq * 4 + 2][nl] = wv.z;
                    ws[kvq * 4 + 3][nl] = wv.w;
                }
                __syncthreads();
#pragma unroll
                for (int kk = 0; kk < 16; kk++) {
                    unsigned long long ar[4];
#pragma unroll
                    for (int r = 0; r < 4; r++) ar[r] = a2s[kk][ty * 4 + r];
                    unsigned long long bg[4];
#pragma unroll
                    for (int g = 0; g < 4; g++)
                        bg[g] = *(const unsigned long long*)&ws[kk][g * 64 + 2 * tx];
#pragma unroll
                    for (int r = 0; r < 4; r++)
#pragma unroll
                        for (int g = 0; g < 4; g++) ffma2(acc[r][g], ar[r], bg[g]);
                }
                __syncthreads();
            }
        }

        // epilogue: add xg, LSTM cell update, store c/h
#pragma unroll
        for (int r = 0; r < 4; r++) {
            int row = ty * 4 + r;             // 0..31
            int L = l0 + row;
            int s = s_base + row;
            const float* xgrow = g_xg
                + ((size_t)((time * SRn + s) * 2 + dir)) * Gn + j0 + 2 * tx;
            float2 xi = *(const float2*)(xgrow + 0 * Hn);
            float2 xf = *(const float2*)(xgrow + 1 * Hn);
            float2 xg = *(const float2*)(xgrow + 2 * Hn);
            float2 xo = *(const float2*)(xgrow + 3 * Hn);

            float pi0 = f2lo(acc[r][0]) + xi.x, pi1 = f2hi(acc[r][0]) + xi.y;
            float pf0 = f2lo(acc[r][1]) + xf.x, pf1 = f2hi(acc[r][1]) + xf.y;
            float pg0 = f2lo(acc[r][2]) + xg.x, pg1 = f2hi(acc[r][2]) + xg.y;
            float po0 = f2lo(acc[r][3]) + xo.x, po1 = f2hi(acc[r][3]) + xo.y;

            float i0 = sigm(pi0), i1 = sigm(pi1);
            float f0 = sigm(pf0), f1 = sigm(pf1);
            float gg0 = tanhf(pg0), gg1 = tanhf(pg1);
            float o0 = sigm(po0), o1 = sigm(po1);

            float c0o = 0.f, c1o = 0.f;
            size_t cidx = (size_t)L * Hn + j0 + 2 * tx;
            if (k > 0) {
                float2 cv = *(const float2*)(g_cc + cidx);
                c0o = cv.x; c1o = cv.y;
            }
            float cn0 = f0 * c0o + i0 * gg0;
            float cn1 = f1 * c1o + i1 * gg1;
            float h0v = o0 * tanhf(cn0);
            float h1v = o1 * tanhf(cn1);

            *(float2*)(g_cc + cidx) = make_float2(cn0, cn1);
            *(float2*)(hnext + cidx) = make_float2(h0v, h1v);
            float* hb = hbuf + (size_t)(time * SRn + s) * (2 * Hn) + dir * Hn
                        + j0 + 2 * tx;
            *(float2*)hb = make_float2(h0v, h1v);
        }

        // per-row-group barrier (8 blocks share rg); skip after last step
        if (k + 1 < Tn) {
            __threadfence();
            __syncthreads();
            if (tid == 0) {
                atomicAdd(&g_bar[rg], 1u);
                unsigned target = 8u * (unsigned)(k + 1);
                volatile unsigned* p = &g_bar[rg];
                while (*p < target) __nanosleep(64);
                __threadfence();
            }
            __syncthreads();
        }
    }
}

// ---------------- output assembly ----------------------------------------------
__global__ void k_out(float* __restrict__ out) {
    int tb = blockIdx.x;
    int t = tb >> 6, b = tb & 63;
    int p = g_spk[b * Tn + t];
    int r = g_pos[b * Tn + t];
    const float4* us = (const float4*)(g_h1 + (size_t)(t * SRn + b) * 1024);
    const float4* up = (const float4*)(g_h1 + (size_t)(r * SRn + 64 + p * 64 + b) * 1024);
    float4* o = (float4*)(out + (size_t)tb * 2048);
    int tid = threadIdx.x;
    o[tid]       = us[tid];   // first 1024 floats: U_s
    o[256 + tid] = up[tid];   // next 1024 floats: U_p
}

// ---------------- launcher ------------------------------------------------------
extern "C" void kernel_launch(void* const* d_in, const int* in_sizes, int n_in,
                              void* d_out, int out_size) {
    const float* U     = (const float*)d_in[0];
    const float* qmask = (const float*)d_in[1];
    const float* rW0 = (const float*)d_in[3];
    const float* rU0 = (const float*)d_in[4];
    const float* rb0 = (const float*)d_in[5];
    const float* rW1 = (const float*)d_in[6];
    const float* rU1 = (const float*)d_in[7];
    const float* rb1 = (const float*)d_in[8];
    const float* pW0 = (const float*)d_in[9];
    const float* pU0 = (const float*)d_in[10];
    const float* pb0 = (const float*)d_in[11];
    const float* pW1 = (const float*)d_in[12];
    const float* pU1 = (const float*)d_in[13];
    const float* pb1 = (const float*)d_in[14];
    float* out = (float*)d_out;

    k_zero_up<<<2048, 256>>>();
    k_prep<<<1, 64>>>(qmask);
    k_scatter<<<Tn * Bn, 256>>>(U);

    dim3 gx(16, (Tn * SRn) / 64);   // 16 x 768

    k_xg<<<gx, 256>>>(0, U, rW0, rb0, pW0, pb0);
    k_bzero<<<1, 32>>>();
    k_rec<<<dim3(12, 8), 256>>>(0, rU0, pU0);

    k_xg<<<gx, 256>>>(1, U, rW1, rb1, pW1, pb1);
    k_bzero<<<1, 32>>>();
    k_rec<<<dim3(12, 8), 256>>>(1, rU1, pU1);

    k_out<<<Tn * Bn, 256>>>(out);
}

// round 6
// speedup vs baseline: 1.0626x; 1.0006x over previous
#include <cuda_runtime.h>
#include <cstdint>
#include <cstddef>

// Problem constants
#define Tn   256
#define Bn   64
#define Dn   1024
#define Hn   512
#define Gn   2048   // 4H
#define PBn  128    // P*B party streams
#define SRn  192    // stream rows per timestep: 64 (rnn) + 128 (rnnp)
#define LANES 384   // SRn * 2 directions

// ---------------- scratch (static device globals; no allocations) -------------
__device__ float g_Up [Tn * PBn * Dn];            // party-gathered inputs
__device__ float g_xg [(size_t)Tn * SRn * 2 * Gn];// input projections (per layer)
__device__ float g_h0 [(size_t)Tn * SRn * 2 * Hn];// layer0 h outputs (fwd|bwd)
__device__ float g_h1 [(size_t)Tn * SRn * 2 * Hn];// layer1 h outputs
__device__ float g_hA [LANES * Hn];               // h double buffer A
__device__ float g_hB [LANES * Hn];               // h double buffer B
__device__ float g_cc [LANES * Hn];               // cell state
__device__ int   g_spk[Bn * Tn];
__device__ int   g_pos[Bn * Tn];
__device__ unsigned g_bar[12];                    // per-row-group step barriers

// ---------------- helpers ------------------------------------------------------
__device__ __forceinline__ void ffma2(unsigned long long &d,
                                      unsigned long long a,
                                      unsigned long long b) {
    asm("fma.rn.f32x2 %0, %1, %2, %0;" : "+l"(d) : "l"(a), "l"(b));
}
__device__ __forceinline__ unsigned long long dup2(float x) {
    unsigned int u = __float_as_uint(x);
    return ((unsigned long long)u << 32) | (unsigned long long)u;
}
__device__ __forceinline__ float f2lo(unsigned long long v) {
    return __uint_as_float((unsigned int)(v & 0xffffffffULL));
}
__device__ __forceinline__ float f2hi(unsigned long long v) {
    return __uint_as_float((unsigned int)(v >> 32));
}
__device__ __forceinline__ float sigm(float x) {
    return __fdividef(1.f, 1.f + __expf(-x));
}

// ---------------- zero the party buffer ----------------------------------------
__global__ void k_zero_up() {
    size_t n4 = (size_t)Tn * PBn * Dn / 4;
    float4 z = make_float4(0.f, 0.f, 0.f, 0.f);
    float4* p = (float4*)g_Up;
    for (size_t i = (size_t)blockIdx.x * blockDim.x + threadIdx.x; i < n4;
         i += (size_t)gridDim.x * blockDim.x)
        p[i] = z;
}

// ---------------- barrier counters reset ----------------------------------------
__global__ void k_bzero() {
    if (threadIdx.x < 12) g_bar[threadIdx.x] = 0u;
}

// ---------------- speaker rank precompute --------------------------------------
__global__ void k_prep(const float* __restrict__ qmask) {
    int b = threadIdx.x;
    if (b >= Bn) return;
    int c0 = 0, c1 = 0;
    for (int t = 0; t < Tn; t++) {
        float q1 = qmask[(b * Tn + t) * 2 + 1];
        int p = (q1 > 0.5f) ? 1 : 0;
        g_spk[b * Tn + t] = p;
        g_pos[b * Tn + t] = p ? (c1++) : (c0++);
    }
}

// ---------------- party gather (scatter U rows into party streams) -------------
__global__ void k_scatter(const float* __restrict__ U) {
    int tb = blockIdx.x;
    int t = tb >> 6, b = tb & 63;
    int p = g_spk[b * Tn + t];
    int r = g_pos[b * Tn + t];
    int s = p * Bn + b;
    const float4* src = (const float4*)(U + (size_t)(t * Bn + b) * Dn);
    float4*       dst = (float4*)(g_Up + (size_t)(r * PBn + s) * Dn);
    dst[threadIdx.x] = src[threadIdx.x];   // 256 threads * float4 = 1024 floats
}

// ---------------- input-projection GEMM (software-pipelined) --------------------
// g_xg[((t*192+s)*2+dir)*2048 + n] = x[t,s,:] . W[dir][n,:] + bias[dir][n]
// Tile: 64 rows x 256 cols, K=1024 in chunks of 16, 256 threads, f32x2 packed.
// Next chunk's global loads are issued before the compute phase so their
// latency hides under the 512-FFMA2 compute.
__global__ __launch_bounds__(256, 2) void k_xg(
    int layer, const float* __restrict__ U,
    const float* __restrict__ WihR, const float* __restrict__ bR,
    const float* __restrict__ WihP, const float* __restrict__ bP)
{
    __shared__ __align__(16) unsigned long long a2s[16][66]; // duplicated x vals
    __shared__ __align__(16) float              bs [16][260]; // weights [k][n]

    int m0  = blockIdx.y * 64;
    int n0g = blockIdx.x * 256;
    int dir = n0g >> 11;
    int n0  = n0g & 2047;
    int t   = m0 / SRn;
    int s0  = m0 - t * SRn;          // 0, 64 or 128
    bool isR = (s0 == 0);

    const float* W    = (isR ? WihR : WihP) + ((size_t)dir * Gn + n0) * 1024;
    const float* bias = (isR ? bR : bP) + dir * Gn + n0;

    int tid = threadIdx.x;
    int tx = tid & 31, ty = tid >> 5;

    int arow = tid >> 2;      // 0..63
    int akv  = tid & 3;       // 0..3
    const float* xrow;
    {
        int s = s0 + arow;
        if (layer == 0) {
            if (isR) xrow = U    + (size_t)(t * Bn  + s) * 1024;
            else     xrow = g_Up + (size_t)(t * PBn + (s - 64)) * 1024;
        } else {
            xrow = g_h0 + (size_t)(t * SRn + s) * 1024;
        }
    }
    const float* wrow = W + (size_t)(tid >> 2) * 1024 + akv * 4;

    unsigned long long acc[8][4];
#pragma unroll
    for (int i = 0; i < 8; i++)
#pragma unroll
        for (int j = 0; j < 4; j++) acc[i][j] = 0ULL;

    // prologue: load chunk 0 into registers
    float4 av = *(const float4*)(xrow + akv * 4);
    float4 wv0 = *(const float4*)(wrow);
    float4 wv1 = *(const float4*)(wrow + 64 * 1024);
    float4 wv2 = *(const float4*)(wrow + 128 * 1024);
    float4 wv3 = *(const float4*)(wrow + 192 * 1024);

    for (int k0 = 0; k0 < 1024; k0 += 16) {
        // store staged chunk into shared
        a2s[akv * 4 + 0][arow] = dup2(av.x);
        a2s[akv * 4 + 1][arow] = dup2(av.y);
        a2s[akv * 4 + 2][arow] = dup2(av.z);
        a2s[akv * 4 + 3][arow] = dup2(av.w);
        {
            int nl = tid >> 2;
            bs[akv * 4 + 0][nl      ] = wv0.x;
            bs[akv * 4 + 1][nl      ] = wv0.y;
            bs[akv * 4 + 2][nl      ] = wv0.z;
            bs[akv * 4 + 3][nl      ] = wv0.w;
            bs[akv * 4 + 0][nl +  64] = wv1.x;
            bs[akv * 4 + 1][nl +  64] = wv1.y;
            bs[akv * 4 + 2][nl +  64] = wv1.z;
            bs[akv * 4 + 3][nl +  64] = wv1.w;
            bs[akv * 4 + 0][nl + 128] = wv2.x;
            bs[akv * 4 + 1][nl + 128] = wv2.y;
            bs[akv * 4 + 2][nl + 128] = wv2.z;
            bs[akv * 4 + 3][nl + 128] = wv2.w;
            bs[akv * 4 + 0][nl + 192] = wv3.x;
            bs[akv * 4 + 1][nl + 192] = wv3.y;
            bs[akv * 4 + 2][nl + 192] = wv3.z;
            bs[akv * 4 + 3][nl + 192] = wv3.w;
        }
        __syncthreads();

        // issue next chunk's loads (latency hides under compute below)
        if (k0 + 16 < 1024) {
            int kn = k0 + 16;
            av  = *(const float4*)(xrow + kn + akv * 4);
            wv0 = *(const float4*)(wrow + kn);
            wv1 = *(const float4*)(wrow + 64 * 1024 + kn);
            wv2 = *(const float4*)(wrow + 128 * 1024 + kn);
            wv3 = *(const float4*)(wrow + 192 * 1024 + kn);
        }

#pragma unroll
        for (int kk = 0; kk < 16; kk++) {
            ulonglong2 A0 = *(const ulonglong2*)&a2s[kk][ty * 4];
            ulonglong2 A1 = *(const ulonglong2*)&a2s[kk][ty * 4 + 2];
            ulonglong2 A2 = *(const ulonglong2*)&a2s[kk][32 + ty * 4];
            ulonglong2 A3 = *(const ulonglong2*)&a2s[kk][32 + ty * 4 + 2];
            ulonglong2 B0 = *(const ulonglong2*)&bs[kk][tx * 4];
            ulonglong2 B1 = *(const ulonglong2*)&bs[kk][128 + tx * 4];
            unsigned long long ar[8] = {A0.x, A0.y, A1.x, A1.y, A2.x, A2.y, A3.x, A3.y};
            unsigned long long bp[4] = {B0.x, B0.y, B1.x, B1.y};
#pragma unroll
            for (int r = 0; r < 8; r++)
#pragma unroll
                for (int c = 0; c < 4; c++) ffma2(acc[r][c], ar[r], bp[c]);
        }
        __syncthreads();
    }

    // epilogue: add bias, store
#pragma unroll
    for (int rh = 0; rh < 2; rh++) {
#pragma unroll
        for (int rq = 0; rq < 4; rq++) {
            int r = (rh ? 32 : 0) + ty * 4 + rq;
            int s = s0 + r;
            float* orow = g_xg + ((size_t)((t * SRn + s) * 2 + dir)) * Gn + n0;
            int ai = rh * 4 + rq;
#pragma unroll
            for (int ch = 0; ch < 2; ch++) {
                int c = (ch ? 128 : 0) + tx * 4;
                unsigned long long p0 = acc[ai][ch * 2 + 0];
                unsigned long long p1 = acc[ai][ch * 2 + 1];
                float4 ov;
                ov.x = f2lo(p0) + bias[c + 0];
                ov.y = f2hi(p0) + bias[c + 1];
                ov.z = f2lo(p1) + bias[c + 2];
                ov.w = f2hi(p1) + bias[c + 3];
                *(float4*)(orow + c) = ov;
            }
        }
    }
}

// ---------------- persistent recurrence (all 256 steps in one launch) ----------
// Grid (12, 8): 96 blocks, all resident (<=148 SMs). Block (rg, jg) owns
// lanes [32rg, 32rg+32) x h-indices [64jg, 64jg+64) x all 4 gates.
// Cross-step dependency: block reads h rows of its OWN lane group only, which
// are written by the 8 jg-blocks sharing rg -> per-rg barrier of 8 arrivals.
__global__ __launch_bounds__(256) void k_rec(
    int layer,
    const float* __restrict__ WhhR, const float* __restrict__ WhhP)
{
    __shared__ __align__(16) unsigned long long a2s[16][34]; // h_prev duplicated
    __shared__ __align__(16) float              ws [16][258]; // weight tile [k][col]

    int rg = blockIdx.x;           // 0..11 : lane group of 32
    int jg = blockIdx.y;           // 0..7  : h-index group of 64
    int l0 = rg * 32;
    int j0 = jg * 64;

    bool isR = (l0 < 128);
    int  dir = isR ? (l0 >= 64 ? 1 : 0) : (l0 >= 256 ? 1 : 0);
    int  L0seg = isR ? (dir ? 64 : 0) : (dir ? 256 : 128);
    int  s_base = (isR ? 0 : 64) + (l0 - L0seg);

    const float* W = (isR ? WhhR : WhhP) + (size_t)dir * Gn * Hn;
    float* hbuf = layer ? g_h1 : g_h0;

    int tid = threadIdx.x;
    int tx = tid & 31, ty = tid >> 5;

    for (int k = 0; k < Tn; k++) {
        int time = dir ? (Tn - 1 - k) : k;
        int parity = k & 1;
        const float* hprev = parity ? g_hB : g_hA;
        float*       hnext = parity ? g_hA : g_hB;

        unsigned long long acc[4][4];   // [row r][gate g]; pair j = j0+2tx, +1
#pragma unroll
        for (int i = 0; i < 4; i++)
#pragma unroll
            for (int j = 0; j < 4; j++) acc[i][j] = 0ULL;

        if (k > 0) {
            for (int k0 = 0; k0 < Hn; k0 += 16) {
                // stage h_prev: 32 rows x 16 k, duplicated
#pragma unroll
                for (int e = 0; e < 2; e++) {
                    int idx = tid + e * 256;
                    int row = idx >> 4, kv = idx & 15;
                    a2s[kv][row] = dup2(hprev[(size_t)(l0 + row) * Hn + k0 + kv]);
                }
                // stage weights: 256 gate-cols (4 gates x 64 j) x 16 k
#pragma unroll
                for (int i = 0; i < 4; i++) {
                    int jj = tid >> 2;              // 0..63
                    int nl = jj + i * 64;           // gate = i
                    int kvq = tid & 3;
                    const float4 wv = *(const float4*)(
                        W + (size_t)(i * Hn + j0 + jj) * Hn + k0 + kvq * 4);
                    ws[kvq * 4 + 0][nl] = wv.x;
                    ws[kvq * 4 + 1][nl] = wv.y;
                    ws[kvq * 4 + 2][nl] = wv.z;
                    ws[kvq * 4 + 3][nl] = wv.w;
                }
                __syncthreads();
#pragma unroll
                for (int kk = 0; kk < 16; kk++) {
                    unsigned long long ar[4];
#pragma unroll
                    for (int r = 0; r < 4; r++) ar[r] = a2s[kk][ty * 4 + r];
                    unsigned long long bg[4];
#pragma unroll
                    for (int g = 0; g < 4; g++)
                        bg[g] = *(const unsigned long long*)&ws[kk][g * 64 + 2 * tx];
#pragma unroll
                    for (int r = 0; r < 4; r++)
#pragma unroll
                        for (int g = 0; g < 4; g++) ffma2(acc[r][g], ar[r], bg[g]);
                }
                __syncthreads();
            }
        }

        // epilogue: add xg, LSTM cell update, store c/h
#pragma unroll
        for (int r = 0; r < 4; r++) {
            int row = ty * 4 + r;             // 0..31
            int L = l0 + row;
            int s = s_base + row;
            const float* xgrow = g_xg
                + ((size_t)((time * SRn + s) * 2 + dir)) * Gn + j0 + 2 * tx;
            float2 xi = *(const float2*)(xgrow + 0 * Hn);
            float2 xf = *(const float2*)(xgrow + 1 * Hn);
            float2 xg = *(const float2*)(xgrow + 2 * Hn);
            float2 xo = *(const float2*)(xgrow + 3 * Hn);

            float pi0 = f2lo(acc[r][0]) + xi.x, pi1 = f2hi(acc[r][0]) + xi.y;
            float pf0 = f2lo(acc[r][1]) + xf.x, pf1 = f2hi(acc[r][1]) + xf.y;
            float pg0 = f2lo(acc[r][2]) + xg.x, pg1 = f2hi(acc[r][2]) + xg.y;
            float po0 = f2lo(acc[r][3]) + xo.x, po1 = f2hi(acc[r][3]) + xo.y;

            float i0 = sigm(pi0), i1 = sigm(pi1);
            float f0 = sigm(pf0), f1 = sigm(pf1);
            float gg0 = tanhf(pg0), gg1 = tanhf(pg1);
            float o0 = sigm(po0), o1 = sigm(po1);

            float c0o = 0.f, c1o = 0.f;
            size_t cidx = (size_t)L * Hn + j0 + 2 * tx;
            if (k > 0) {
                float2 cv = *(const float2*)(g_cc + cidx);
                c0o = cv.x; c1o = cv.y;
            }
            float cn0 = f0 * c0o + i0 * gg0;
            float cn1 = f1 * c1o + i1 * gg1;
            float h0v = o0 * tanhf(cn0);
            float h1v = o1 * tanhf(cn1);

            *(float2*)(g_cc + cidx) = make_float2(cn0, cn1);
            *(float2*)(hnext + cidx) = make_float2(h0v, h1v);
            float* hb = hbuf + (size_t)(time * SRn + s) * (2 * Hn) + dir * Hn
                        + j0 + 2 * tx;
            *(float2*)hb = make_float2(h0v, h1v);
        }

        // per-row-group barrier (8 blocks share rg); skip after last step
        if (k + 1 < Tn) {
            __threadfence();
            __syncthreads();
            if (tid == 0) {
                atomicAdd(&g_bar[rg], 1u);
                unsigned target = 8u * (unsigned)(k + 1);
                volatile unsigned* p = &g_bar[rg];
                while (*p < target) __nanosleep(64);
                __threadfence();
            }
            __syncthreads();
        }
    }
}

// ---------------- output assembly ----------------------------------------------
__global__ void k_out(float* __restrict__ out) {
    int tb = blockIdx.x;
    int t = tb >> 6, b = tb & 63;
    int p = g_spk[b * Tn + t];
    int r = g_pos[b * Tn + t];
    const float4* us = (const float4*)(g_h1 + (size_t)(t * SRn + b) * 1024);
    const float4* up = (const float4*)(g_h1 + (size_t)(r * SRn + 64 + p * 64 + b) * 1024);
    float4* o = (float4*)(out + (size_t)tb * 2048);
    int tid = threadIdx.x;
    o[tid]       = us[tid];   // first 1024 floats: U_s
    o[256 + tid] = up[tid];   // next 1024 floats: U_p
}

// ---------------- launcher ------------------------------------------------------
extern "C" void kernel_launch(void* const* d_in, const int* in_sizes, int n_in,
                              void* d_out, int out_size) {
    const float* U     = (const float*)d_in[0];
    const float* qmask = (const float*)d_in[1];
    const float* rW0 = (const float*)d_in[3];
    const float* rU0 = (const float*)d_in[4];
    const float* rb0 = (const float*)d_in[5];
    const float* rW1 = (const float*)d_in[6];
    const float* rU1 = (const float*)d_in[7];
    const float* rb1 = (const float*)d_in[8];
    const float* pW0 = (const float*)d_in[9];
    const float* pU0 = (const float*)d_in[10];
    const float* pb0 = (const float*)d_in[11];
    const float* pW1 = (const float*)d_in[12];
    const float* pU1 = (const float*)d_in[13];
    const float* pb1 = (const float*)d_in[14];
    float* out = (float*)d_out;

    k_zero_up<<<2048, 256>>>();
    k_prep<<<1, 64>>>(qmask);
    k_scatter<<<Tn * Bn, 256>>>(U);

    dim3 gx(16, (Tn * SRn) / 64);   // 16 x 768

    k_xg<<<gx, 256>>>(0, U, rW0, rb0, pW0, pb0);
    k_bzero<<<1, 32>>>();
    k_rec<<<dim3(12, 8), 256>>>(0, rU0, pU0);

    k_xg<<<gx, 256>>>(1, U, rW1, rb1, pW1, pb1);
    k_bzero<<<1, 32>>>();
    k_rec<<<dim3(12, 8), 256>>>(1, rU1, pU1);

    k_out<<<Tn * Bn, 256>>>(out);
}